// round 8
// baseline (speedup 1.0000x reference)
#include <cuda_runtime.h>

// EA-LSTM fused persistent kernel, round 7: 2-way k-split (512 thr, best base)
// + slim packed weights (float2 f,o + float g) + fully parallel state update
// (partner-exchange partials, c/ig in registers of the updating thread)
// + conflict-free transposed h for the output dot. Static SMEM only.
// B=1024, T=365, Dd=32, Ds=27, H=256, 3H=768, O=1.
// Grid: 128 CTAs x 512 threads, M=8 batch elems per CTA.
// Unified reduction axis K = 32 (x) + 256 (h) = 288. Thread (col, half):
//   phase A: partial gates f/o/g of col over k in [144*half, 144*half+144)
//   exchange: publish the 2 m-pair partials the partner needs (6 u64),
//             read 6 u64 back -> each thread updates c/h for its own 4 m's.
// All accumulation bit-exact fp32 (Blackwell packed f32x2).

#define B_      1024
#define T_      365
#define DD      32
#define DS      27
#define H_      256
#define G3      768
#define M_      8
#define KTOT    288
#define KG      144            // k per half
#define THREADS 512
#define CTAS    (B_ / M_)      // 128
#define PSTRIDE 258            // padded u64 stride for partials
#define HT_S    264            // padded row stride for transposed h

typedef unsigned long long u64;

// slim packed weights over the unified k axis (k<32 -> W_ih row, else W_hh)
__device__ float2 WfoP[KTOT][256];   // (wf, wo) per column
__device__ float  WgP [KTOT][256];   // wg per column

__device__ __forceinline__ u64 pack2(float lo, float hi) {
    u64 r; asm("mov.b64 %0, {%1, %2};" : "=l"(r) : "f"(lo), "f"(hi)); return r;
}
__device__ __forceinline__ void unpack2(u64 v, float& lo, float& hi) {
    asm("mov.b64 {%0, %1}, %2;" : "=f"(lo), "=f"(hi) : "l"(v));
}
__device__ __forceinline__ void fma2(u64& d, u64 a, u64 b) {
    asm("fma.rn.f32x2 %0, %1, %2, %0;" : "+l"(d) : "l"(a), "l"(b));
}
__device__ __forceinline__ void add2(u64& d, u64 a) {
    asm("add.rn.f32x2 %0, %0, %1;" : "+l"(d) : "l"(a));
}
__device__ __forceinline__ float sigmoidf_(float x) {
    return __fdividef(1.0f, 1.0f + __expf(-x));
}
__device__ __forceinline__ float tanhf_(float x) {
    float e = __expf(-2.0f * x);
    return __fdividef(1.0f - e, 1.0f + e);
}

__global__ void __launch_bounds__(256)
repack_kernel(const float* __restrict__ Wih, const float* __restrict__ Whh) {
    const int i   = blockIdx.x * blockDim.x + threadIdx.x;  // 0 .. 288*256-1
    const int k   = i >> 8;
    const int col = i & 255;
    const float* s = (k < DD) ? (Wih + k * G3) : (Whh + (k - DD) * G3);
    WfoP[k][col] = make_float2(s[col], s[256 + col]);
    WgP [k][col] = s[512 + col];
}

__global__ void __launch_bounds__(THREADS, 1)
ealstm_kernel(const float* __restrict__ xd,      // [B, T, DD]
              const float* __restrict__ xs,      // [B, DS]
              const float* __restrict__ Wsh,     // [DS, H]
              const float* __restrict__ bias,    // [3H]
              const float* __restrict__ bias_s,  // [H]
              const float* __restrict__ Wout,    // [H, 1]
              const float* __restrict__ bout,    // [1]
              float* __restrict__ out)           // [B, T, 1]
{
    __shared__ __align__(16) float xh[KTOT * M_];  // k<32: x_t, k>=32: h (stride 8)
    __shared__ u64   pub[12][PSTRIDE];             // partner-exchange partials
    __shared__ float h_t[M_][HT_S];                // transposed h for out-dot

    const int tid  = threadIdx.x;
    const int half = tid >> 8;              // 0 or 1
    const int col  = tid & 255;
    const int b0   = blockIdx.x * M_;
    const int lane = tid & 31;
    const int warp = tid >> 5;
    const int k0   = half * KG;
    const int pA   = 2 * half;              // my m-pairs: pA, pA+1 (m = 4*half..)
    const int pP   = 2 * (1 - half);        // partner's m-pairs (I publish these)

    // zero h region of xh
    for (int i = DD * M_ + tid; i < KTOT * M_; i += THREADS) xh[i] = 0.0f;

    // stage x_t for t = 0 (half 0)
    if (half == 0) {
        const int m = col >> 5, k = col & 31;
        xh[k * M_ + m] = xd[((size_t)(b0 + m) * T_ + 0) * DD + k];
    }

    // biases: half 0 seeds accumulators (full sums = half0 + half1)
    float bf = 0.0f, bo = 0.0f, bg = 0.0f;
    if (half == 0) { bf = bias[col]; bo = bias[H_ + col]; bg = bias[2 * H_ + col]; }

    // per-thread cell state + entity-aware input gate for OWN 4 batch elems
    float c[4], ig[4];
    {
        float s[4];
        const float bs = bias_s[col];
        #pragma unroll
        for (int i = 0; i < 4; i++) { s[i] = bs; c[i] = 0.0f; }
        #pragma unroll 1
        for (int k = 0; k < DS; k++) {
            const float w = Wsh[k * H_ + col];
            #pragma unroll
            for (int i = 0; i < 4; i++)
                s[i] = fmaf(xs[(b0 + 4 * half + i) * DS + k], w, s[i]);
        }
        #pragma unroll
        for (int i = 0; i < 4; i++) ig[i] = sigmoidf_(s[i]);
    }

    // out-dot weights (half-1 warps do the dot)
    float wout[8];
    #pragma unroll
    for (int q = 0; q < 8; q++) wout[q] = Wout[lane + 32 * q];
    const float b_out0 = bout[0];

    __syncthreads();

    for (int t = 0; t < T_; t++) {
        // ---- phase A: partial gate sums over this half's k range ----
        u64 aF[4], aO[4], aG[4];
        {
            const u64 bf2 = pack2(bf, bf), bo2 = pack2(bo, bo), bg2 = pack2(bg, bg);
            #pragma unroll
            for (int p = 0; p < 4; p++) { aF[p] = bf2; aO[p] = bo2; aG[p] = bg2; }
        }
        {
            const float2* wfo_p = &WfoP[k0][col];
            const float*  wg_p  = &WgP[k0][col];
            const float*  hb    = xh + k0 * M_;
            #pragma unroll 4
            for (int k = 0; k < KG; k++) {
                const float2 wfo = __ldcg(wfo_p + k * 256);
                const float  wg  = __ldcg(wg_p  + k * 256);
                const u64 wf2 = pack2(wfo.x, wfo.x);
                const u64 wo2 = pack2(wfo.y, wfo.y);
                const u64 wg2 = pack2(wg, wg);
                const ulonglong2 hA = *(const ulonglong2*)(hb + k * M_);
                const ulonglong2 hB = *(const ulonglong2*)(hb + k * M_ + 4);
                fma2(aF[0], wf2, hA.x); fma2(aF[1], wf2, hA.y);
                fma2(aF[2], wf2, hB.x); fma2(aF[3], wf2, hB.y);
                fma2(aO[0], wo2, hA.x); fma2(aO[1], wo2, hA.y);
                fma2(aO[2], wo2, hB.x); fma2(aO[3], wo2, hB.y);
                fma2(aG[0], wg2, hA.x); fma2(aG[1], wg2, hA.y);
                fma2(aG[2], wg2, hB.x); fma2(aG[3], wg2, hB.y);
            }
        }

        // publish the partner's m-pairs (disjoint slots per half -> no race)
        pub[0 + pP][col] = aF[pP];  pub[0 + pP + 1][col] = aF[pP + 1];
        pub[4 + pP][col] = aO[pP];  pub[4 + pP + 1][col] = aO[pP + 1];
        pub[8 + pP][col] = aG[pP];  pub[8 + pP + 1][col] = aG[pP + 1];

        __syncthreads();   // partials exchanged; xh reads of step t done

        // ---- parallel state update: own 2 m-pairs (m = 4*half .. 4*half+3) ----
        {
            float hn[4];
            #pragma unroll
            for (int i = 0; i < 2; i++) {
                const int p = pA + i;
                u64 tF = aF[p], tO = aO[p], tG = aG[p];
                add2(tF, pub[0 + p][col]);
                add2(tO, pub[4 + p][col]);
                add2(tG, pub[8 + p][col]);
                float f0, f1, o0, o1, g0, g1;
                unpack2(tF, f0, f1);
                unpack2(tO, o0, o1);
                unpack2(tG, g0, g1);
                const int i0 = 2 * i, i1 = 2 * i + 1;
                c[i0] = sigmoidf_(f0) * c[i0] + ig[i0] * tanhf_(g0);
                c[i1] = sigmoidf_(f1) * c[i1] + ig[i1] * tanhf_(g1);
                hn[i0] = sigmoidf_(o0) * tanhf_(c[i0]);
                hn[i1] = sigmoidf_(o1) * tanhf_(c[i1]);
            }
            // publish h slice (16B-aligned float4) + transposed copy
            *(float4*)(xh + (DD + col) * M_ + 4 * half) =
                make_float4(hn[0], hn[1], hn[2], hn[3]);
            h_t[4 * half + 0][col] = hn[0];
            h_t[4 * half + 1][col] = hn[1];
            h_t[4 * half + 2][col] = hn[2];
            h_t[4 * half + 3][col] = hn[3];
        }

        // half 0 stages x for t+1 (x region: disjoint from h region)
        if (half == 0 && t + 1 < T_) {
            const int m = col >> 5, k = col & 31;
            xh[k * M_ + m] = xd[((size_t)(b0 + m) * T_ + (t + 1)) * DD + k];
        }

        __syncthreads();   // h(t), h_t(t), x(t+1) published

        // ---- output dot (half-1 warps 8..15, batch elem w = warp-8) ----
        // h_t is not rewritten until the update phase of t+1 (after that
        // step's first barrier, which these warps reach only after the dot).
        if (half == 1) {
            const int w = warp - 8;
            float a = 0.0f;
            #pragma unroll
            for (int q = 0; q < 8; q++)
                a = fmaf(h_t[w][lane + 32 * q], wout[q], a);
            #pragma unroll
            for (int off = 16; off > 0; off >>= 1)
                a += __shfl_down_sync(0xffffffffu, a, off);
            if (lane == 0)
                out[(size_t)(b0 + w) * T_ + t] = a + b_out0;
        }
    }
}

extern "C" void kernel_launch(void* const* d_in, const int* in_sizes, int n_in,
                              void* d_out, int out_size) {
    const float* xd     = (const float*)d_in[0];  // x_dynamic [1024,365,32]
    const float* xs     = (const float*)d_in[1];  // x_static  [1024,27]
    const float* Wih    = (const float*)d_in[2];  // [32,768]
    const float* Whh    = (const float*)d_in[3];  // [256,768]
    const float* Wsh    = (const float*)d_in[4];  // [27,256]
    const float* bias   = (const float*)d_in[5];  // [768]
    const float* bias_s = (const float*)d_in[6];  // [256]
    const float* Wout   = (const float*)d_in[7];  // [256,1]
    const float* bout   = (const float*)d_in[8];  // [1]
    float* out = (float*)d_out;                   // [1024,365,1]

    repack_kernel<<<KTOT, 256>>>(Wih, Whh);
    ealstm_kernel<<<CTAS, THREADS>>>(xd, xs, Wsh, bias, bias_s,
                                     Wout, bout, out);
}